// round 1
// baseline (speedup 1.0000x reference)
#include <cuda_runtime.h>

#define N_ROWS 65536
#define DIM    512
#define KC     256
#define BM     64      // rows per block
#define DT     16      // d-chunk
#define NTHR   256

// Pre-transposed centroid scratch: g_ct2[d][kp] = (c[2kp][d], c[2kp+1][d])
__device__ float2 g_ct2[DIM][KC / 2];
__device__ float  g_cnorm[KC];

__device__ __forceinline__ unsigned long long pack2(float x, float y) {
    unsigned long long r;
    asm("mov.b64 %0, {%1, %2};" : "=l"(r) : "f"(x), "f"(y));
    return r;
}
__device__ __forceinline__ void fma2(unsigned long long& d, unsigned long long a, unsigned long long b) {
    asm("fma.rn.f32x2 %0, %1, %2, %0;" : "+l"(d) : "l"(a), "l"(b));
}
__device__ __forceinline__ void add2(unsigned long long& d, unsigned long long a) {
    asm("add.rn.f32x2 %0, %0, %1;" : "+l"(d) : "l"(a));
}
__device__ __forceinline__ float2 unpack2(unsigned long long v) {
    float2 r;
    asm("mov.b64 {%0, %1}, %2;" : "=f"(r.x), "=f"(r.y) : "l"(v));
    return r;
}

// ---------------------------------------------------------------------------
// Prep: transpose centroids into paired layout + exact (fp64-accumulated) norms
// ---------------------------------------------------------------------------
__global__ void prep_kernel(const float* __restrict__ cent) {
    __shared__ double red[4];
    const int k   = blockIdx.x;
    const int tid = threadIdx.x;   // 128 threads
    const float* row = cent + (size_t)k * DIM;
    double s = 0.0;
    for (int d = tid; d < DIM; d += 128) {
        float v = row[d];
        s += (double)v * (double)v;
        ((float*)(&g_ct2[d][k >> 1]))[k & 1] = v;
    }
    #pragma unroll
    for (int o = 16; o; o >>= 1) s += __shfl_xor_sync(0xffffffffu, s, o);
    if ((tid & 31) == 0) red[tid >> 5] = s;
    __syncthreads();
    if (tid == 0) g_cnorm[k] = (float)(red[0] + red[1] + red[2] + red[3]);
}

// ---------------------------------------------------------------------------
// Main fused kernel: scores (f32x2 FMA) -> per-row top-2 -> gather output
// Thread (cx = lane, ry = warp): rows [8*ry, 8*ry+8), centroid pairs
// {cx, cx+32, cx+64, cx+96} (i.e. centroids 2kp, 2kp+1).
// score[n][k] = |c_k|^2 - 2 * <e_n, c_k>   (|e_n|^2 constant per row, dropped)
// ---------------------------------------------------------------------------
__global__ __launch_bounds__(NTHR) void main_kernel(
    const float* __restrict__ E, const float* __restrict__ C, float* __restrict__ out)
{
    __shared__ __align__(16) unsigned long long e2s[DT][66];   // duplicated e, pitch 66
    __shared__ __align__(16) float2 c2s[DT][KC / 2];
    __shared__ float cn[KC];
    __shared__ int   idx2_s[BM];

    const int tid  = threadIdx.x;
    const int cx   = tid & 31;
    const int ry   = tid >> 5;
    const int row0 = blockIdx.x * BM;

    for (int i = tid; i < KC; i += NTHR) cn[i] = g_cnorm[i];

    unsigned long long acc[8][4];
    #pragma unroll
    for (int j = 0; j < 8; j++)
        #pragma unroll
        for (int p = 0; p < 4; p++) acc[j][p] = 0ull;

    // staging (software pipeline: LDG for chunk i+1 in flight during compute of i)
    const int er = tid >> 2;   // row 0..63
    const int eq = tid & 3;    // float4-quad within DT
    float4 estage;
    float4 cstage[4];

    estage = *(const float4*)(E + (size_t)(row0 + er) * DIM + eq * 4);
    #pragma unroll
    for (int j = 0; j < 4; j++) {
        int u = tid + NTHR * j;          // 1024 float4 units (16 d x 64 units)
        int dd = u >> 6, c4 = u & 63;
        cstage[j] = *((const float4*)(&g_ct2[dd][0]) + c4);
    }

    for (int ch = 0; ch < DIM / DT; ch++) {
        // ---- store staged tile to smem ----
        e2s[eq * 4 + 0][er] = pack2(estage.x, estage.x);
        e2s[eq * 4 + 1][er] = pack2(estage.y, estage.y);
        e2s[eq * 4 + 2][er] = pack2(estage.z, estage.z);
        e2s[eq * 4 + 3][er] = pack2(estage.w, estage.w);
        #pragma unroll
        for (int j = 0; j < 4; j++) {
            int u = tid + NTHR * j;
            int dd = u >> 6, c4 = u & 63;
            *((float4*)(&c2s[dd][0]) + c4) = cstage[j];
        }
        __syncthreads();

        // ---- prefetch next chunk (overlaps compute below) ----
        if (ch + 1 < DIM / DT) {
            int c0 = (ch + 1) * DT;
            estage = *(const float4*)(E + (size_t)(row0 + er) * DIM + c0 + eq * 4);
            #pragma unroll
            for (int j = 0; j < 4; j++) {
                int u = tid + NTHR * j;
                int dd = u >> 6, c4 = u & 63;
                cstage[j] = *((const float4*)(&g_ct2[c0 + dd][0]) + c4);
            }
        }

        // ---- compute chunk into fresh accumulators (chunked summation) ----
        unsigned long long cacc[8][4];
        #pragma unroll
        for (int j = 0; j < 8; j++)
            #pragma unroll
            for (int p = 0; p < 4; p++) cacc[j][p] = 0ull;

        #pragma unroll
        for (int dd = 0; dd < DT; dd++) {
            unsigned long long ev[8];
            #pragma unroll
            for (int j = 0; j < 8; j++) ev[j] = e2s[dd][ry * 8 + j];   // warp broadcast
            unsigned long long cv[4];
            #pragma unroll
            for (int p = 0; p < 4; p++)
                cv[p] = *(const unsigned long long*)(&c2s[dd][cx + 32 * p]); // stride-8B, conflict-free
            #pragma unroll
            for (int j = 0; j < 8; j++)
                #pragma unroll
                for (int p = 0; p < 4; p++)
                    fma2(cacc[j][p], ev[j], cv[p]);
        }
        #pragma unroll
        for (int j = 0; j < 8; j++)
            #pragma unroll
            for (int p = 0; p < 4; p++) add2(acc[j][p], cacc[j][p]);
        __syncthreads();
    }

    // ---- per-row top-2 (value asc, index asc tie-break — matches jax top_k) ----
    #pragma unroll
    for (int j = 0; j < 8; j++) {
        float bv1 = 3.4e38f, bv2 = 3.4e38f;
        int   bi1 = 0x7fffffff, bi2 = 0x7fffffff;
        #pragma unroll
        for (int p = 0; p < 4; p++) {
            int kp = cx + 32 * p;
            float2 d = unpack2(acc[j][p]);
            float s0 = cn[2 * kp]     - 2.0f * d.x;
            float s1 = cn[2 * kp + 1] - 2.0f * d.y;
            int   i0 = 2 * kp, i1 = 2 * kp + 1;
            if (s0 < bv1 || (s0 == bv1 && i0 < bi1)) { bv2 = bv1; bi2 = bi1; bv1 = s0; bi1 = i0; }
            else if (s0 < bv2 || (s0 == bv2 && i0 < bi2)) { bv2 = s0; bi2 = i0; }
            if (s1 < bv1 || (s1 == bv1 && i1 < bi1)) { bv2 = bv1; bi2 = bi1; bv1 = s1; bi1 = i1; }
            else if (s1 < bv2 || (s1 == bv2 && i1 < bi2)) { bv2 = s1; bi2 = i1; }
        }
        #pragma unroll
        for (int off = 16; off; off >>= 1) {
            float ov1 = __shfl_xor_sync(0xffffffffu, bv1, off);
            int   oi1 = __shfl_xor_sync(0xffffffffu, bi1, off);
            float ov2 = __shfl_xor_sync(0xffffffffu, bv2, off);
            int   oi2 = __shfl_xor_sync(0xffffffffu, bi2, off);
            if (ov1 < bv1 || (ov1 == bv1 && oi1 < bi1)) { bv2 = bv1; bi2 = bi1; bv1 = ov1; bi1 = oi1; }
            else if (ov1 < bv2 || (ov1 == bv2 && oi1 < bi2)) { bv2 = ov1; bi2 = oi1; }
            if (ov2 < bv1 || (ov2 == bv1 && oi2 < bi1)) { bv2 = bv1; bi2 = bi1; bv1 = ov2; bi1 = oi2; }
            else if (ov2 < bv2 || (ov2 == bv2 && oi2 < bi2)) { bv2 = ov2; bi2 = oi2; }
        }
        if (cx == 0) idx2_s[ry * 8 + j] = bi2;
    }
    __syncthreads();

    // ---- gather: out[row] = centroids[idx2[row]]  (centroids are L2-hot) ----
    for (int t = tid; t < BM * (DIM / 4); t += NTHR) {
        int r = t >> 7;             // 128 float4 per row
        int q = t & 127;
        int src = idx2_s[r];
        *(float4*)(out + (size_t)(row0 + r) * DIM + q * 4) =
            *(const float4*)(C + (size_t)src * DIM + q * 4);
    }
}

extern "C" void kernel_launch(void* const* d_in, const int* in_sizes, int n_in,
                              void* d_out, int out_size) {
    const float* E = (const float*)d_in[0];   // embeddings [65536, 512] f32
    const float* C = (const float*)d_in[1];   // centroids  [256, 512]   f32
    float* out = (float*)d_out;               // [65536, 512] f32
    (void)in_sizes; (void)n_in; (void)out_size;

    prep_kernel<<<KC, 128>>>(C);
    main_kernel<<<N_ROWS / BM, NTHR>>>(E, C, out);
}